// round 7
// baseline (speedup 1.0000x reference)
#include <cuda_runtime.h>
#include <cuda_bf16.h>
#include <cstdint>
#include <math.h>

#define BATCH 2
#define SEQ   2048
#define EMB   1024
#define NHEAD 16
#define HDIM  64
#define M_ROWS (BATCH*SEQ)      // 4096
#define QKV_N  (3*EMB)          // 3072

// ---------------- scratch (device globals, no allocation) ----------------
__device__ float g_T[HDIM*HDIM];
__device__ float g_Wf[EMB*QKV_N];                // folded + RNA-tf32
__device__ float g_WoR[(size_t)EMB*EMB];         // RNA(Wout)
__device__ float g_bf[QKV_N];
__device__ float g_xr[(size_t)M_ROWS*EMB];       // RNA(x)
__device__ float g_qkv[(size_t)M_ROWS*QKV_N];    // RNA'd by GEMM epilogue
__device__ float g_attn[(size_t)M_ROWS*EMB];     // RNA'd by attn epilogue

__device__ __forceinline__ unsigned f2tf(float f) {
    unsigned u;
    asm("cvt.rna.tf32.f32 %0, %1;" : "=r"(u) : "f"(f));
    return u;
}
__device__ __forceinline__ float rnaf(float f) { return __uint_as_float(f2tf(f)); }

__device__ __forceinline__ uint32_t smem_u32(const void* p) {
    uint32_t a;
    asm("{ .reg .u64 t; cvta.to.shared.u64 t, %1; cvt.u32.u64 %0, t; }"
        : "=r"(a) : "l"(p));
    return a;
}

__device__ __forceinline__ void cp16(uint32_t dst, const void* src) {
    asm volatile("cp.async.cg.shared.global [%0], [%1], 16;" :: "r"(dst), "l"(src));
}
#define CP_COMMIT() asm volatile("cp.async.commit_group;" ::: "memory")
#define CP_WAIT(n)  asm volatile("cp.async.wait_group %0;" :: "n"(n) : "memory")

__device__ __forceinline__ void mma_tf32(float c[4],
                                         unsigned a0, unsigned a1, unsigned a2, unsigned a3,
                                         unsigned b0, unsigned b1) {
    asm volatile(
        "mma.sync.aligned.m16n8k8.row.col.f32.tf32.tf32.f32 "
        "{%0,%1,%2,%3}, {%4,%5,%6,%7}, {%8,%9}, {%0,%1,%2,%3};"
        : "+f"(c[0]), "+f"(c[1]), "+f"(c[2]), "+f"(c[3])
        : "r"(a0), "r"(a1), "r"(a2), "r"(a3), "r"(b0), "r"(b1));
}

// ---------------- build T = I + (alpha/64) * H diag H --------------------
__global__ void build_T_kernel(const float* __restrict__ diag,
                               const float* __restrict__ alpha_p) {
    int i = blockIdx.x, j = threadIdx.x;
    float a = alpha_p[0] * (1.0f / 64.0f);
    int ij = i ^ j;
    float acc = 0.f;
    #pragma unroll
    for (int k = 0; k < 64; k++)
        acc += diag[k] * ((__popc(ij & k) & 1) ? -1.f : 1.f);
    g_T[i*64 + j] = a * acc + ((i == j) ? 1.f : 0.f);
}

// ---------------- fold T into QKV weights, smem-tiled ---------------------
// block: 64-row x 64-col tile; q/k blocks multiply by T, v blocks copy.
__global__ __launch_bounds__(256)
void fold_w_tiled(const float* __restrict__ W) {
    __shared__ float Wt[64][65];
    __shared__ float Tt[64][65];
    int jb = blockIdx.x;   // 0..47
    int eb = blockIdx.y;   // 0..15
    int tid = threadIdx.x;

    #pragma unroll
    for (int i = tid; i < 4096; i += 256) {
        int r = i >> 6, c = i & 63;
        Wt[r][c] = W[(size_t)(eb*64 + r)*QKV_N + jb*64 + c];
        Tt[r][c] = g_T[r*64 + c];
    }
    __syncthreads();

    if (jb < 32) {
        int r = tid >> 2;
        int c0 = (tid & 3) * 16;
        float acc[16];
        #pragma unroll
        for (int j = 0; j < 16; j++) acc[j] = 0.f;
        #pragma unroll 8
        for (int d = 0; d < 64; d++) {
            float w = Wt[r][d];
            #pragma unroll
            for (int j = 0; j < 16; j++)
                acc[j] += w * Tt[d][c0 + j];
        }
        size_t orow = (size_t)(eb*64 + r)*QKV_N + jb*64 + c0;
        #pragma unroll
        for (int j = 0; j < 16; j++)
            g_Wf[orow + j] = rnaf(acc[j]);
    } else {
        #pragma unroll
        for (int i = tid; i < 4096; i += 256) {
            int r = i >> 6, c = i & 63;
            g_Wf[(size_t)(eb*64 + r)*QKV_N + jb*64 + c] = rnaf(Wt[r][c]);
        }
    }
}

__global__ void fold_b_kernel(const float* __restrict__ bqkv,
                              const float* __restrict__ bias_h) {
    int c = blockIdx.x * blockDim.x + threadIdx.x;
    if (c >= QKV_N) return;
    if (c < 2*EMB) {
        int j = c & 63;
        int base = c - j;
        float acc = bias_h[j];
        #pragma unroll 8
        for (int d = 0; d < 64; d++)
            acc += bqkv[base + d] * g_T[d*64 + j];
        g_bf[c] = acc;
    } else {
        g_bf[c] = bqkv[c];
    }
}

// ---------------- elementwise RNA-to-tf32 ---------------------------------
__global__ void rna_kernel(const float* __restrict__ in, float* __restrict__ out, int n4) {
    int i = blockIdx.x * blockDim.x + threadIdx.x;
    if (i >= n4) return;
    float4 v = ((const float4*)in)[i];
    v.x = rnaf(v.x); v.y = rnaf(v.y); v.z = rnaf(v.z); v.w = rnaf(v.w);
    ((float4*)out)[i] = v;
}

// ---------------- tf32 GEMM: C = A@B + bias, cp.async 3-stage, 1 sync -----
#define AP2 20
#define BP2 264
#define ASTG (128*AP2)
#define BSTG (16*BP2)
#define GSTG (ASTG + BSTG)
#define GEMM_SMEM (3*GSTG*4)
__global__ __launch_bounds__(256, 1)
void gemm_tf32_kernel(const float* __restrict__ A,
                      const float* __restrict__ B,
                      const float* __restrict__ bias,
                      float* __restrict__ C,
                      int M, int N, int K, int roundOut) {
    extern __shared__ unsigned sh[];
    uint32_t shA = smem_u32(sh);

    int tid = threadIdx.x;
    int warp = tid >> 5, lane = tid & 31;
    int tig = lane & 3, gid = lane >> 2;
    int warpM = warp & 1, warpN = warp >> 1;
    int m0 = blockIdx.y * 128;
    int n0 = blockIdx.x * 256;

    float c[4][8][4];
    #pragma unroll
    for (int mf = 0; mf < 4; mf++)
        #pragma unroll
        for (int nf = 0; nf < 8; nf++)
            #pragma unroll
            for (int j = 0; j < 4; j++) c[mf][nf][j] = 0.f;

    int nk = K / 16;

    auto issue = [&](int s, int k0) {
        uint32_t base = shA + (uint32_t)s * GSTG * 4;
        #pragma unroll
        for (int i = 0; i < 2; i++) {
            int li = tid + i*256;
            int row = li >> 2, kq = li & 3;
            cp16(base + (row*AP2 + kq*4)*4, A + (size_t)(m0 + row)*K + k0 + kq*4);
        }
        #pragma unroll
        for (int i = 0; i < 4; i++) {
            int li = tid + i*256;
            int kr = li >> 6, nq = li & 63;
            cp16(base + (ASTG + kr*BP2 + nq*4)*4, B + (size_t)(k0 + kr)*N + n0 + nq*4);
        }
        CP_COMMIT();
    };

    issue(0, 0);
    issue(1, 16);

    for (int kt = 0; kt < nk; kt++) {
        if (kt + 1 < nk) { CP_WAIT(1); } else { CP_WAIT(0); }
        __syncthreads();
        if (kt + 2 < nk) issue((kt + 2) % 3, (kt + 2) * 16);

        unsigned* Ab = sh + (kt % 3) * GSTG;
        unsigned* Bb = Ab + ASTG;

        #pragma unroll
        for (int kk = 0; kk < 16; kk += 8) {
            unsigned af[4][4];
            #pragma unroll
            for (int mf = 0; mf < 4; mf++) {
                int m = warpM*64 + mf*16 + gid;
                af[mf][0] = Ab[m*AP2 + kk + tig];
                af[mf][1] = Ab[(m+8)*AP2 + kk + tig];
                af[mf][2] = Ab[m*AP2 + kk + tig + 4];
                af[mf][3] = Ab[(m+8)*AP2 + kk + tig + 4];
            }
            unsigned bf[8][2];
            #pragma unroll
            for (int nf = 0; nf < 8; nf++) {
                int n = warpN*64 + nf*8 + gid;
                bf[nf][0] = Bb[(kk+tig  )*BP2 + n];
                bf[nf][1] = Bb[(kk+tig+4)*BP2 + n];
            }
            #pragma unroll
            for (int mf = 0; mf < 4; mf++)
                #pragma unroll
                for (int nf = 0; nf < 8; nf++)
                    mma_tf32(c[mf][nf], af[mf][0], af[mf][1], af[mf][2], af[mf][3],
                             bf[nf][0], bf[nf][1]);
        }
    }

    #pragma unroll
    for (int mf = 0; mf < 4; mf++) {
        int row = m0 + warpM*64 + mf*16 + gid;
        #pragma unroll
        for (int nf = 0; nf < 8; nf++) {
            int col = n0 + warpN*64 + nf*8 + 2*tig;
            float b0 = bias[col], b1 = bias[col+1];
            float v00 = c[mf][nf][0] + b0, v01 = c[mf][nf][1] + b1;
            float v10 = c[mf][nf][2] + b0, v11 = c[mf][nf][3] + b1;
            if (roundOut) { v00 = rnaf(v00); v01 = rnaf(v01); v10 = rnaf(v10); v11 = rnaf(v11); }
            *(float2*)&C[(size_t)row * N + col]     = make_float2(v00, v01);
            *(float2*)&C[(size_t)(row+8) * N + col] = make_float2(v10, v11);
        }
    }
}

// ---------------- flash attention, tf32, shfl-P, Q frags in regs ----------
#define QP 68
#define VP 72
#define KSTG (64*QP)
#define VSTG (64*VP)
#define ATTN_SMEM ((128*QP + 2*KSTG + 2*VSTG)*4 + 2*64*4)
__global__ __launch_bounds__(256, 2)
void attn_tf32_kernel(const float* __restrict__ qkv,
                      const int* __restrict__ mask,
                      float* __restrict__ out) {
    extern __shared__ unsigned smU[];
    unsigned* Qs = smU;                     // [128][68]
    unsigned* Ks = Qs + 128*QP;             // [2][64][68]
    unsigned* Vs = Ks + 2*KSTG;             // [2][64][72]
    int*      Ms = (int*)(Vs + 2*VSTG);     // [2][64]

    uint32_t kA = smem_u32(Ks);
    uint32_t vA = smem_u32(Vs);
    uint32_t mA = smem_u32(Ms);

    int bh = blockIdx.x;
    int b = bh >> 4, h = bh & 15;
    int q0 = blockIdx.y * 128;

    int tid = threadIdx.x;
    int warp = tid >> 5, lane = tid & 31;
    int tig = lane & 3, gid = lane >> 2;
    int row0 = warp*16 + gid, row1 = row0 + 8;
    int srcL = (gid << 2) | (tig >> 1);
    int srcH = srcL + 2;
    bool odd = (tig & 1);

    const size_t rs = QKV_N;
    const float* qbase = qkv + (size_t)(b*SEQ)*rs + h*HDIM;
    const float* kbase = qbase + EMB;
    const float* vbase = qbase + 2*EMB;
    const int*   mrow  = mask + b*SEQ;

    auto issue = [&](int s, int k0) {
        #pragma unroll
        for (int i = 0; i < 4; i++) {
            int li = tid + i*256;
            int r = li >> 4, dq = (li & 15) * 4;
            cp16(kA + (s*KSTG + r*QP + dq)*4, kbase + (size_t)(k0 + r)*rs + dq);
            cp16(vA + (s*VSTG + r*VP + dq)*4, vbase + (size_t)(k0 + r)*rs + dq);
        }
        if (tid < 16) cp16(mA + s*256 + tid*16, mrow + k0 + tid*4);
        CP_COMMIT();
    };

    // load Q tile (values already tf32-rounded by QKV GEMM epilogue)
    #pragma unroll
    for (int i = 0; i < 8; i++) {
        int li = tid + i*256;
        int r = li >> 4, dq = (li & 15) * 4;
        uint4 v = *(const uint4*)&qbase[(size_t)(q0 + r)*rs + dq];
        *(uint4*)&Qs[r*QP + dq] = v;
    }

    issue(0, 0);
    issue(1, 64);

    // hoist loop-invariant Q fragments to registers
    __syncthreads();
    unsigned qf[8][4];
    #pragma unroll
    for (int k8 = 0; k8 < 8; k8++) {
        int kk = k8 * 8;
        qf[k8][0] = Qs[row0*QP + kk + tig];
        qf[k8][1] = Qs[row1*QP + kk + tig];
        qf[k8][2] = Qs[row0*QP + kk + tig + 4];
        qf[k8][3] = Qs[row1*QP + kk + tig + 4];
    }

    float o[8][4];
    #pragma unroll
    for (int nf = 0; nf < 8; nf++)
        #pragma unroll
        for (int j = 0; j < 4; j++) o[nf][j] = 0.f;
    float m0r = -1e30f, m1r = -1e30f, l0 = 0.f, l1 = 0.f;

    const int NT = SEQ / 64;
    for (int kt = 0; kt < NT; kt++) {
        int st = kt & 1;
        if (kt + 1 < NT) { CP_WAIT(1); } else { CP_WAIT(0); }
        __syncthreads();

        unsigned* Kb = Ks + st*KSTG;
        unsigned* Vb = Vs + st*VSTG;
        int*      Mb = Ms + st*64;

        // S = Q K^T
        float s[8][4];
        #pragma unroll
        for (int nf = 0; nf < 8; nf++)
            #pragma unroll
            for (int j = 0; j < 4; j++) s[nf][j] = 0.f;
        #pragma unroll
        for (int k8 = 0; k8 < 8; k8++) {
            int kk = k8 * 8;
            #pragma unroll
            for (int nf = 0; nf < 8; nf++) {
                unsigned b0 = Kb[(nf*8 + gid)*QP + kk + tig];
                unsigned b1 = Kb[(nf*8 + gid)*QP + kk + tig + 4];
                mma_tf32(s[nf], qf[k8][0], qf[k8][1], qf[k8][2], qf[k8][3], b0, b1);
            }
        }

        #pragma unroll
        for (int nf = 0; nf < 8; nf++) {
            int col = nf*8 + 2*tig;
            int mv0 = Mb[col], mv1 = Mb[col+1];
            s[nf][0] = mv0 ? s[nf][0]*0.125f : -1e30f;
            s[nf][1] = mv1 ? s[nf][1]*0.125f : -1e30f;
            s[nf][2] = mv0 ? s[nf][2]*0.125f : -1e30f;
            s[nf][3] = mv1 ? s[nf][3]*0.125f : -1e30f;
        }

        float rm0 = -1e30f, rm1 = -1e30f;
        #pragma unroll
        for (int nf = 0; nf < 8; nf++) {
            rm0 = fmaxf(rm0, fmaxf(s[nf][0], s[nf][1]));
            rm1 = fmaxf(rm1, fmaxf(s[nf][2], s[nf][3]));
        }
        rm0 = fmaxf(rm0, __shfl_xor_sync(0xffffffffu, rm0, 1));
        rm0 = fmaxf(rm0, __shfl_xor_sync(0xffffffffu, rm0, 2));
        rm1 = fmaxf(rm1, __shfl_xor_sync(0xffffffffu, rm1, 1));
        rm1 = fmaxf(rm1, __shfl_xor_sync(0xffffffffu, rm1, 2));

        float mn0 = fmaxf(m0r, rm0), mn1 = fmaxf(m1r, rm1);
        float sc0 = __expf(m0r - mn0), sc1 = __expf(m1r - mn1);
        m0r = mn0; m1r = mn1;

        float rs0 = 0.f, rs1 = 0.f;
        #pragma unroll
        for (int nf = 0; nf < 8; nf++) {
            s[nf][0] = __expf(s[nf][0] - mn0);
            s[nf][1] = __expf(s[nf][1] - mn0);
            s[nf][2] = __expf(s[nf][2] - mn1);
            s[nf][3] = __expf(s[nf][3] - mn1);
            rs0 += s[nf][0] + s[nf][1];
            rs1 += s[nf][2] + s[nf][3];
        }
        rs0 += __shfl_xor_sync(0xffffffffu, rs0, 1);
        rs0 += __shfl_xor_sync(0xffffffffu, rs0, 2);
        rs1 += __shfl_xor_sync(0xffffffffu, rs1, 1);
        rs1 += __shfl_xor_sync(0xffffffffu, rs1, 2);
        l0 = l0*sc0 + rs0;
        l1 = l1*sc1 + rs1;

        #pragma unroll
        for (int nf = 0; nf < 8; nf++) {
            o[nf][0] *= sc0; o[nf][1] *= sc0;
            o[nf][2] *= sc1; o[nf][3] *= sc1;
            s[nf][0] = rnaf(s[nf][0]); s[nf][1] = rnaf(s[nf][1]);
            s[nf][2] = rnaf(s[nf][2]); s[nf][3] = rnaf(s[nf][3]);
        }

        // O += P @ V ; P A-fragments gathered via shfl from S C-fragments.
        #pragma unroll
        for (int kk = 0; kk < 64; kk += 8) {
            int nfs = kk >> 3;
            float e00 = __shfl_sync(0xffffffffu, s[nfs][0], srcL);
            float e01 = __shfl_sync(0xffffffffu, s[nfs][1], srcL);
            float e10 = __shfl_sync(0xffffffffu, s[nfs][2], srcL);
            float e11 = __shfl_sync(0xffffffffu, s[nfs][3], srcL);
            float f00 = __shfl_sync(0xffffffffu, s[nfs][0], srcH);
            float f01 = __shfl_sync(0xffffffffu, s[nfs][1], srcH);
            float f10 = __shfl_sync(0xffffffffu, s[nfs][2], srcH);
            float f11 = __shfl_sync(0xffffffffu, s[nfs][3], srcH);
            unsigned a0 = __float_as_uint(odd ? e01 : e00);
            unsigned a1 = __float_as_uint(odd ? e11 : e10);
            unsigned a2 = __float_as_uint(odd ? f01 : f00);
            unsigned a3 = __float_as_uint(odd ? f11 : f10);
            #pragma unroll
            for (int nf = 0; nf < 8; nf++) {
                unsigned b0 = Vb[(kk + tig)*VP + nf*8 + gid];
                unsigned b1 = Vb[(kk + tig + 4)*VP + nf*8 + gid];
                mma_tf32(o[nf], a0, a1, a2, a3, b0, b1);
            }
        }
        __syncthreads();
        if (kt + 2 < NT) issue(st, (kt + 2) * 64);
    }

    // epilogue: normalize + RNA (consumed by out-proj GEMM)
    float inv0 = 1.f / l0, inv1 = 1.f / l1;
    #pragma unroll
    for (int nf = 0; nf < 8; nf++) {
        int col = nf*8 + 2*tig;
        size_t orow0 = (size_t)(b*SEQ + q0 + row0) * EMB + h*HDIM + col;
        size_t orow1 = (size_t)(b*SEQ + q0 + row1) * EMB + h*HDIM + col;
        *(float2*)&out[orow0] = make_float2(rnaf(o[nf][0]*inv0), rnaf(o[nf][1]*inv0));
        *(float2*)&out[orow1] = make_float2(rnaf(o[nf][2]*inv1), rnaf(o[nf][3]*inv1));
    }
}

// ---------------- launch ---------------------------------------------------
extern "C" void kernel_launch(void* const* d_in, const int* in_sizes, int n_in,
                              void* d_out, int out_size) {
    const float* x      = (const float*)d_in[0];
    const int*   mask   = (const int*)  d_in[1];
    const float* Wqkv   = (const float*)d_in[2];
    const float* bqkv   = (const float*)d_in[3];
    const float* Wout   = (const float*)d_in[4];
    const float* bout   = (const float*)d_in[5];
    const float* diag   = (const float*)d_in[6];
    const float* alpha  = (const float*)d_in[7];
    const float* bias_h = (const float*)d_in[8];
    float* out = (float*)d_out;

    float* qkv;  cudaGetSymbolAddress((void**)&qkv,  g_qkv);
    float* attn; cudaGetSymbolAddress((void**)&attn, g_attn);
    float* Wf;   cudaGetSymbolAddress((void**)&Wf,   g_Wf);
    float* WoR;  cudaGetSymbolAddress((void**)&WoR,  g_WoR);
    float* bf;   cudaGetSymbolAddress((void**)&bf,   g_bf);
    float* xr;   cudaGetSymbolAddress((void**)&xr,   g_xr);

    build_T_kernel<<<64, 64>>>(diag, alpha);
    {
        dim3 grid(48, 16);
        fold_w_tiled<<<grid, 256>>>(Wqkv);
        fold_b_kernel<<<(QKV_N + 255)/256, 256>>>(bqkv, bias_h);
        int n4x = M_ROWS*EMB/4;
        rna_kernel<<<(n4x + 255)/256, 256>>>(x, xr, n4x);
        int n4w = EMB*EMB/4;
        rna_kernel<<<(n4w + 255)/256, 256>>>(Wout, WoR, n4w);
    }

    cudaFuncSetAttribute(gemm_tf32_kernel,
                         cudaFuncAttributeMaxDynamicSharedMemorySize, GEMM_SMEM);
    {   // QKV GEMM: [4096,1024] @ [1024,3072], output RNA'd
        dim3 grid(QKV_N/256, M_ROWS/128);
        gemm_tf32_kernel<<<grid, 256, GEMM_SMEM>>>(xr, Wf, bf, qkv,
                                                   M_ROWS, QKV_N, EMB, 1);
    }
    {   // attention
        cudaFuncSetAttribute(attn_tf32_kernel,
                             cudaFuncAttributeMaxDynamicSharedMemorySize, ATTN_SMEM);
        dim3 grid(BATCH*NHEAD, SEQ/128);
        attn_tf32_kernel<<<grid, 256, ATTN_SMEM>>>(qkv, mask, attn);
    }
    {   // output projection: [4096,1024] @ [1024,1024], exact fp32 out
        dim3 grid(EMB/256, M_ROWS/128);
        gemm_tf32_kernel<<<grid, 256, GEMM_SMEM>>>(attn, WoR, bout, out,
                                                   M_ROWS, EMB, EMB, 0);
    }
}

// round 8
// speedup vs baseline: 1.0233x; 1.0233x over previous
#include <cuda_runtime.h>
#include <cuda_bf16.h>
#include <cstdint>
#include <math.h>

#define BATCH 2
#define SEQ   2048
#define EMB   1024
#define NHEAD 16
#define HDIM  64
#define M_ROWS (BATCH*SEQ)      // 4096
#define QKV_N  (3*EMB)          // 3072

// ---------------- scratch (device globals, no allocation) ----------------
__device__ float g_T[HDIM*HDIM];
__device__ float g_Wf[EMB*QKV_N];                // folded + RNA-tf32
__device__ float g_WoR[(size_t)EMB*EMB];         // RNA(Wout)
__device__ float g_bf[QKV_N];
__device__ float g_xr[(size_t)M_ROWS*EMB];       // RNA(x)
__device__ float g_qkv[(size_t)M_ROWS*QKV_N];    // RNA'd by GEMM epilogue
__device__ float g_attn[(size_t)M_ROWS*EMB];     // RNA'd by attn epilogue

__device__ __forceinline__ unsigned f2tf(float f) {
    unsigned u;
    asm("cvt.rna.tf32.f32 %0, %1;" : "=r"(u) : "f"(f));
    return u;
}
__device__ __forceinline__ float rnaf(float f) { return __uint_as_float(f2tf(f)); }

__device__ __forceinline__ uint32_t smem_u32(const void* p) {
    uint32_t a;
    asm("{ .reg .u64 t; cvta.to.shared.u64 t, %1; cvt.u32.u64 %0, t; }"
        : "=r"(a) : "l"(p));
    return a;
}

__device__ __forceinline__ void cp16(uint32_t dst, const void* src) {
    asm volatile("cp.async.cg.shared.global [%0], [%1], 16;" :: "r"(dst), "l"(src));
}
#define CP_COMMIT() asm volatile("cp.async.commit_group;" ::: "memory")
#define CP_WAIT(n)  asm volatile("cp.async.wait_group %0;" :: "n"(n) : "memory")

__device__ __forceinline__ void mma_tf32(float c[4],
                                         unsigned a0, unsigned a1, unsigned a2, unsigned a3,
                                         unsigned b0, unsigned b1) {
    asm volatile(
        "mma.sync.aligned.m16n8k8.row.col.f32.tf32.tf32.f32 "
        "{%0,%1,%2,%3}, {%4,%5,%6,%7}, {%8,%9}, {%0,%1,%2,%3};"
        : "+f"(c[0]), "+f"(c[1]), "+f"(c[2]), "+f"(c[3])
        : "r"(a0), "r"(a1), "r"(a2), "r"(a3), "r"(b0), "r"(b1));
}

// ---------------- build T = I + (alpha/64) * H diag H --------------------
__global__ void build_T_kernel(const float* __restrict__ diag,
                               const float* __restrict__ alpha_p) {
    int i = blockIdx.x, j = threadIdx.x;
    float a = alpha_p[0] * (1.0f / 64.0f);
    int ij = i ^ j;
    float acc = 0.f;
    #pragma unroll
    for (int k = 0; k < 64; k++)
        acc += diag[k] * ((__popc(ij & k) & 1) ? -1.f : 1.f);
    g_T[i*64 + j] = a * acc + ((i == j) ? 1.f : 0.f);
}

// ---------------- fold T into QKV weights, smem-tiled ---------------------
__global__ __launch_bounds__(256)
void fold_w_tiled(const float* __restrict__ W) {
    __shared__ float Wt[64][65];
    __shared__ float Tt[64][65];
    int jb = blockIdx.x;   // 0..47
    int eb = blockIdx.y;   // 0..15
    int tid = threadIdx.x;

    #pragma unroll
    for (int i = tid; i < 4096; i += 256) {
        int r = i >> 6, c = i & 63;
        Wt[r][c] = W[(size_t)(eb*64 + r)*QKV_N + jb*64 + c];
        Tt[r][c] = g_T[r*64 + c];
    }
    __syncthreads();

    if (jb < 32) {
        int r = tid >> 2;
        int c0 = (tid & 3) * 16;
        float acc[16];
        #pragma unroll
        for (int j = 0; j < 16; j++) acc[j] = 0.f;
        #pragma unroll 8
        for (int d = 0; d < 64; d++) {
            float w = Wt[r][d];
            #pragma unroll
            for (int j = 0; j < 16; j++)
                acc[j] += w * Tt[d][c0 + j];
        }
        size_t orow = (size_t)(eb*64 + r)*QKV_N + jb*64 + c0;
        #pragma unroll
        for (int j = 0; j < 16; j++)
            g_Wf[orow + j] = rnaf(acc[j]);
    } else {
        #pragma unroll
        for (int i = tid; i < 4096; i += 256) {
            int r = i >> 6, c = i & 63;
            g_Wf[(size_t)(eb*64 + r)*QKV_N + jb*64 + c] = rnaf(Wt[r][c]);
        }
    }
}

__global__ void fold_b_kernel(const float* __restrict__ bqkv,
                              const float* __restrict__ bias_h) {
    int c = blockIdx.x * blockDim.x + threadIdx.x;
    if (c >= QKV_N) return;
    if (c < 2*EMB) {
        int j = c & 63;
        int base = c - j;
        float acc = bias_h[j];
        #pragma unroll 8
        for (int d = 0; d < 64; d++)
            acc += bqkv[base + d] * g_T[d*64 + j];
        g_bf[c] = acc;
    } else {
        g_bf[c] = bqkv[c];
    }
}

// ---------------- elementwise RNA-to-tf32 ---------------------------------
__global__ void rna_kernel(const float* __restrict__ in, float* __restrict__ out, int n4) {
    int i = blockIdx.x * blockDim.x + threadIdx.x;
    if (i >= n4) return;
    float4 v = ((const float4*)in)[i];
    v.x = rnaf(v.x); v.y = rnaf(v.y); v.z = rnaf(v.z); v.w = rnaf(v.w);
    ((float4*)out)[i] = v;
}

// ---------------- tf32 GEMM: C = A@B + bias, cp.async 3-stage, 1 sync -----
#define AP2 20
#define BP2 264
#define ASTG (128*AP2)
#define BSTG (16*BP2)
#define GSTG (ASTG + BSTG)
#define GEMM_SMEM (3*GSTG*4)
__global__ __launch_bounds__(256, 1)
void gemm_tf32_kernel(const float* __restrict__ A,
                      const float* __restrict__ B,
                      const float* __restrict__ bias,
                      float* __restrict__ C,
                      int M, int N, int K, int roundOut) {
    extern __shared__ unsigned sh[];
    uint32_t shA = smem_u32(sh);

    int tid = threadIdx.x;
    int warp = tid >> 5, lane = tid & 31;
    int tig = lane & 3, gid = lane >> 2;
    int warpM = warp & 1, warpN = warp >> 1;
    int m0 = blockIdx.y * 128;
    int n0 = blockIdx.x * 256;

    float c[4][8][4];
    #pragma unroll
    for (int mf = 0; mf < 4; mf++)
        #pragma unroll
        for (int nf = 0; nf < 8; nf++)
            #pragma unroll
            for (int j = 0; j < 4; j++) c[mf][nf][j] = 0.f;

    int nk = K / 16;

    auto issue = [&](int s, int k0) {
        uint32_t base = shA + (uint32_t)s * GSTG * 4;
        #pragma unroll
        for (int i = 0; i < 2; i++) {
            int li = tid + i*256;
            int row = li >> 2, kq = li & 3;
            cp16(base + (row*AP2 + kq*4)*4, A + (size_t)(m0 + row)*K + k0 + kq*4);
        }
        #pragma unroll
        for (int i = 0; i < 4; i++) {
            int li = tid + i*256;
            int kr = li >> 6, nq = li & 63;
            cp16(base + (ASTG + kr*BP2 + nq*4)*4, B + (size_t)(k0 + kr)*N + n0 + nq*4);
        }
        CP_COMMIT();
    };

    issue(0, 0);
    issue(1, 16);

    for (int kt = 0; kt < nk; kt++) {
        if (kt + 1 < nk) { CP_WAIT(1); } else { CP_WAIT(0); }
        __syncthreads();
        if (kt + 2 < nk) issue((kt + 2) % 3, (kt + 2) * 16);

        unsigned* Ab = sh + (kt % 3) * GSTG;
        unsigned* Bb = Ab + ASTG;

        #pragma unroll
        for (int kk = 0; kk < 16; kk += 8) {
            unsigned af[4][4];
            #pragma unroll
            for (int mf = 0; mf < 4; mf++) {
                int m = warpM*64 + mf*16 + gid;
                af[mf][0] = Ab[m*AP2 + kk + tig];
                af[mf][1] = Ab[(m+8)*AP2 + kk + tig];
                af[mf][2] = Ab[m*AP2 + kk + tig + 4];
                af[mf][3] = Ab[(m+8)*AP2 + kk + tig + 4];
            }
            unsigned bf[8][2];
            #pragma unroll
            for (int nf = 0; nf < 8; nf++) {
                int n = warpN*64 + nf*8 + gid;
                bf[nf][0] = Bb[(kk+tig  )*BP2 + n];
                bf[nf][1] = Bb[(kk+tig+4)*BP2 + n];
            }
            #pragma unroll
            for (int mf = 0; mf < 4; mf++)
                #pragma unroll
                for (int nf = 0; nf < 8; nf++)
                    mma_tf32(c[mf][nf], af[mf][0], af[mf][1], af[mf][2], af[mf][3],
                             bf[nf][0], bf[nf][1]);
        }
    }

    #pragma unroll
    for (int mf = 0; mf < 4; mf++) {
        int row = m0 + warpM*64 + mf*16 + gid;
        #pragma unroll
        for (int nf = 0; nf < 8; nf++) {
            int col = n0 + warpN*64 + nf*8 + 2*tig;
            float b0 = bias[col], b1 = bias[col+1];
            float v00 = c[mf][nf][0] + b0, v01 = c[mf][nf][1] + b1;
            float v10 = c[mf][nf][2] + b0, v11 = c[mf][nf][3] + b1;
            if (roundOut) { v00 = rnaf(v00); v01 = rnaf(v01); v10 = rnaf(v10); v11 = rnaf(v11); }
            *(float2*)&C[(size_t)row * N + col]     = make_float2(v00, v01);
            *(float2*)&C[(size_t)(row+8) * N + col] = make_float2(v10, v11);
        }
    }
}

// ---------------- flash attention, tf32, shfl-P (R6 form) -----------------
#define QP 68
#define VP 72
#define KSTG (64*QP)
#define VSTG (64*VP)
#define ATTN_SMEM ((128*QP + 2*KSTG + 2*VSTG)*4 + 2*64*4)
__global__ __launch_bounds__(256, 2)
void attn_tf32_kernel(const float* __restrict__ qkv,
                      const int* __restrict__ mask,
                      float* __restrict__ out) {
    extern __shared__ unsigned smU[];
    unsigned* Qs = smU;                     // [128][68]
    unsigned* Ks = Qs + 128*QP;             // [2][64][68]
    unsigned* Vs = Ks + 2*KSTG;             // [2][64][72]
    int*      Ms = (int*)(Vs + 2*VSTG);     // [2][64]

    uint32_t kA = smem_u32(Ks);
    uint32_t vA = smem_u32(Vs);
    uint32_t mA = smem_u32(Ms);

    int bh = blockIdx.x;
    int b = bh >> 4, h = bh & 15;
    int q0 = blockIdx.y * 128;

    int tid = threadIdx.x;
    int warp = tid >> 5, lane = tid & 31;
    int tig = lane & 3, gid = lane >> 2;
    int row0 = warp*16 + gid, row1 = row0 + 8;
    int srcL = (gid << 2) | (tig >> 1);
    int srcH = srcL + 2;
    bool odd = (tig & 1);

    const size_t rs = QKV_N;
    const float* qbase = qkv + (size_t)(b*SEQ)*rs + h*HDIM;
    const float* kbase = qbase + EMB;
    const float* vbase = qbase + 2*EMB;
    const int*   mrow  = mask + b*SEQ;

    auto issue = [&](int s, int k0) {
        #pragma unroll
        for (int i = 0; i < 4; i++) {
            int li = tid + i*256;
            int r = li >> 4, dq = (li & 15) * 4;
            cp16(kA + (s*KSTG + r*QP + dq)*4, kbase + (size_t)(k0 + r)*rs + dq);
            cp16(vA + (s*VSTG + r*VP + dq)*4, vbase + (size_t)(k0 + r)*rs + dq);
        }
        if (tid < 16) cp16(mA + s*256 + tid*16, mrow + k0 + tid*4);
        CP_COMMIT();
    };

    // load Q tile (values already tf32-rounded by QKV GEMM epilogue)
    #pragma unroll
    for (int i = 0; i < 8; i++) {
        int li = tid + i*256;
        int r = li >> 4, dq = (li & 15) * 4;
        uint4 v = *(const uint4*)&qbase[(size_t)(q0 + r)*rs + dq];
        *(uint4*)&Qs[r*QP + dq] = v;
    }

    issue(0, 0);
    issue(1, 64);

    float o[8][4];
    #pragma unroll
    for (int nf = 0; nf < 8; nf++)
        #pragma unroll
        for (int j = 0; j < 4; j++) o[nf][j] = 0.f;
    float m0r = -1e30f, m1r = -1e30f, l0 = 0.f, l1 = 0.f;

    const int NT = SEQ / 64;
    for (int kt = 0; kt < NT; kt++) {
        int st = kt & 1;
        if (kt + 1 < NT) { CP_WAIT(1); } else { CP_WAIT(0); }
        __syncthreads();

        unsigned* Kb = Ks + st*KSTG;
        unsigned* Vb = Vs + st*VSTG;
        int*      Mb = Ms + st*64;

        // S = Q K^T
        float s[8][4];
        #pragma unroll
        for (int nf = 0; nf < 8; nf++)
            #pragma unroll
            for (int j = 0; j < 4; j++) s[nf][j] = 0.f;
        #pragma unroll
        for (int kk = 0; kk < 64; kk += 8) {
            unsigned a0 = Qs[row0*QP + kk + tig];
            unsigned a1 = Qs[row1*QP + kk + tig];
            unsigned a2 = Qs[row0*QP + kk + tig + 4];
            unsigned a3 = Qs[row1*QP + kk + tig + 4];
            #pragma unroll
            for (int nf = 0; nf < 8; nf++) {
                unsigned b0 = Kb[(nf*8 + gid)*QP + kk + tig];
                unsigned b1 = Kb[(nf*8 + gid)*QP + kk + tig + 4];
                mma_tf32(s[nf], a0, a1, a2, a3, b0, b1);
            }
        }

        #pragma unroll
        for (int nf = 0; nf < 8; nf++) {
            int col = nf*8 + 2*tig;
            int mv0 = Mb[col], mv1 = Mb[col+1];
            s[nf][0] = mv0 ? s[nf][0]*0.125f : -1e30f;
            s[nf][1] = mv1 ? s[nf][1]*0.125f : -1e30f;
            s[nf][2] = mv0 ? s[nf][2]*0.125f : -1e30f;
            s[nf][3] = mv1 ? s[nf][3]*0.125f : -1e30f;
        }

        float rm0 = -1e30f, rm1 = -1e30f;
        #pragma unroll
        for (int nf = 0; nf < 8; nf++) {
            rm0 = fmaxf(rm0, fmaxf(s[nf][0], s[nf][1]));
            rm1 = fmaxf(rm1, fmaxf(s[nf][2], s[nf][3]));
        }
        rm0 = fmaxf(rm0, __shfl_xor_sync(0xffffffffu, rm0, 1));
        rm0 = fmaxf(rm0, __shfl_xor_sync(0xffffffffu, rm0, 2));
        rm1 = fmaxf(rm1, __shfl_xor_sync(0xffffffffu, rm1, 1));
        rm1 = fmaxf(rm1, __shfl_xor_sync(0xffffffffu, rm1, 2));

        float mn0 = fmaxf(m0r, rm0), mn1 = fmaxf(m1r, rm1);
        float sc0 = __expf(m0r - mn0), sc1 = __expf(m1r - mn1);
        m0r = mn0; m1r = mn1;

        float rs0 = 0.f, rs1 = 0.f;
        #pragma unroll
        for (int nf = 0; nf < 8; nf++) {
            s[nf][0] = __expf(s[nf][0] - mn0);
            s[nf][1] = __expf(s[nf][1] - mn0);
            s[nf][2] = __expf(s[nf][2] - mn1);
            s[nf][3] = __expf(s[nf][3] - mn1);
            rs0 += s[nf][0] + s[nf][1];
            rs1 += s[nf][2] + s[nf][3];
        }
        rs0 += __shfl_xor_sync(0xffffffffu, rs0, 1);
        rs0 += __shfl_xor_sync(0xffffffffu, rs0, 2);
        rs1 += __shfl_xor_sync(0xffffffffu, rs1, 1);
        rs1 += __shfl_xor_sync(0xffffffffu, rs1, 2);
        l0 = l0*sc0 + rs0;
        l1 = l1*sc1 + rs1;

        #pragma unroll
        for (int nf = 0; nf < 8; nf++) {
            o[nf][0] *= sc0; o[nf][1] *= sc0;
            o[nf][2] *= sc1; o[nf][3] *= sc1;
            s[nf][0] = rnaf(s[nf][0]); s[nf][1] = rnaf(s[nf][1]);
            s[nf][2] = rnaf(s[nf][2]); s[nf][3] = rnaf(s[nf][3]);
        }

        // O += P @ V ; P A-fragments gathered via shfl from S C-fragments.
        #pragma unroll
        for (int kk = 0; kk < 64; kk += 8) {
            int nfs = kk >> 3;
            float e00 = __shfl_sync(0xffffffffu, s[nfs][0], srcL);
            float e01 = __shfl_sync(0xffffffffu, s[nfs][1], srcL);
            float e10 = __shfl_sync(0xffffffffu, s[nfs][2], srcL);
            float e11 = __shfl_sync(0xffffffffu, s[nfs][3], srcL);
            float f00 = __shfl_sync(0xffffffffu, s[nfs][0], srcH);
            float f01 = __shfl_sync(0xffffffffu, s[nfs][1], srcH);
            float f10 = __shfl_sync(0xffffffffu, s[nfs][2], srcH);
            float f11 = __shfl_sync(0xffffffffu, s[nfs][3], srcH);
            unsigned a0 = __float_as_uint(odd ? e01 : e00);
            unsigned a1 = __float_as_uint(odd ? e11 : e10);
            unsigned a2 = __float_as_uint(odd ? f01 : f00);
            unsigned a3 = __float_as_uint(odd ? f11 : f10);
            #pragma unroll
            for (int nf = 0; nf < 8; nf++) {
                unsigned b0 = Vb[(kk + tig)*VP + nf*8 + gid];
                unsigned b1 = Vb[(kk + tig + 4)*VP + nf*8 + gid];
                mma_tf32(o[nf], a0, a1, a2, a3, b0, b1);
            }
        }
        __syncthreads();
        if (kt + 2 < NT) issue(st, (kt + 2) * 64);
    }

    // epilogue: normalize + RNA (consumed by out-proj GEMM)
    float inv0 = 1.f / l0, inv1 = 1.f / l1;
    #pragma unroll
    for (int nf = 0; nf < 8; nf++) {
        int col = nf*8 + 2*tig;
        size_t orow0 = (size_t)(b*SEQ + q0 + row0) * EMB + h*HDIM + col;
        size_t orow1 = (size_t)(b*SEQ + q0 + row1) * EMB + h*HDIM + col;
        *(float2*)&out[orow0] = make_float2(rnaf(o[nf][0]*inv0), rnaf(o[nf][1]*inv0));
        *(float2*)&out[orow1] = make_float2(rnaf(o[nf][2]*inv1), rnaf(o[nf][3]*inv1));
    }
}

// ---------------- launch ---------------------------------------------------
extern "C" void kernel_launch(void* const* d_in, const int* in_sizes, int n_in,
                              void* d_out, int out_size) {
    const float* x      = (const float*)d_in[0];
    const int*   mask   = (const int*)  d_in[1];
    const float* Wqkv   = (const float*)d_in[2];
    const float* bqkv   = (const float*)d_in[3];
    const float* Wout   = (const float*)d_in[4];
    const float* bout   = (const float*)d_in[5];
    const float* diag   = (const float*)d_in[6];
    const float* alpha  = (const float*)d_in[7];
    const float* bias_h = (const float*)d_in[8];
    float* out = (float*)d_out;

    float* qkv;  cudaGetSymbolAddress((void**)&qkv,  g_qkv);
    float* attn; cudaGetSymbolAddress((void**)&attn, g_attn);
    float* Wf;   cudaGetSymbolAddress((void**)&Wf,   g_Wf);
    float* WoR;  cudaGetSymbolAddress((void**)&WoR,  g_WoR);
    float* bf;   cudaGetSymbolAddress((void**)&bf,   g_bf);
    float* xr;   cudaGetSymbolAddress((void**)&xr,   g_xr);

    build_T_kernel<<<64, 64>>>(diag, alpha);
    {
        dim3 grid(48, 16);
        fold_w_tiled<<<grid, 256>>>(Wqkv);
        fold_b_kernel<<<(QKV_N + 255)/256, 256>>>(bqkv, bias_h);
        int n4x = M_ROWS*EMB/4;
        rna_kernel<<<(n4x + 255)/256, 256>>>(x, xr, n4x);
        int n4w = EMB*EMB/4;
        rna_kernel<<<(n4w + 255)/256, 256>>>(Wout, WoR, n4w);
    }

    cudaFuncSetAttribute(gemm_tf32_kernel,
                         cudaFuncAttributeMaxDynamicSharedMemorySize, GEMM_SMEM);
    {   // QKV GEMM: [4096,1024] @ [1024,3072], output RNA'd
        dim3 grid(QKV_N/256, M_ROWS/128);
        gemm_tf32_kernel<<<grid, 256, GEMM_SMEM>>>(xr, Wf, bf, qkv,
                                                   M_ROWS, QKV_N, EMB, 1);
    }
    {   // attention
        cudaFuncSetAttribute(attn_tf32_kernel,
                             cudaFuncAttributeMaxDynamicSharedMemorySize, ATTN_SMEM);
        dim3 grid(BATCH*NHEAD, SEQ/128);
        attn_tf32_kernel<<<grid, 256, ATTN_SMEM>>>(qkv, mask, attn);
    }
    {   // output projection: [4096,1024] @ [1024,1024], exact fp32 out
        dim3 grid(EMB/256, M_ROWS/128);
        gemm_tf32_kernel<<<grid, 256, GEMM_SMEM>>>(attn, WoR, bout, out,
                                                   M_ROWS, EMB, EMB, 0);
    }
}